// round 14
// baseline (speedup 1.0000x reference)
#include <cuda_runtime.h>
#include <cstdint>

// Dendrite_54417235641041 — GB300 sm_103a
// y[b,d] = sum_{v=0..255} LWv[v] * prod_{i in bits(v)} t_i,  t_i = sigmoid(k*(w*x-q))[7-i]
// LWv[0] = lin_b, LWv[v] = lin_w[v-1].
// R13 (resubmit; prior round was an infra failure): low nibble -> packed f32x2
// dot with subset-product table (8 fma2/row); high nibble -> STREAMING 4-level
// Horner tree in u0..u3 (15 scalar FMA, no Phi table, no per-iter phi multiply,
// no pk2 dup glue). 2 (b,d) outputs/thread.

#define THREADS 128
#define BPB 8   // b-values per block: 4 warps x 2 b each; lane = d

__device__ __forceinline__ unsigned long long pk2(float lo, float hi) {
    unsigned long long r;
    asm("mov.b64 %0, {%1, %2};" : "=l"(r) : "f"(lo), "f"(hi));
    return r;
}
__device__ __forceinline__ void upk2(unsigned long long v, float& lo, float& hi) {
    asm("mov.b64 {%0, %1}, %2;" : "=f"(lo), "=f"(hi) : "l"(v));
}
__device__ __forceinline__ unsigned long long fma2(unsigned long long a,
                                                   unsigned long long b,
                                                   unsigned long long c) {
    unsigned long long r;
    asm("fma.rn.f32x2 %0, %1, %2, %3;" : "=l"(r) : "l"(a), "l"(b), "l"(c));
    return r;
}
__device__ __forceinline__ unsigned long long mul2_(unsigned long long a,
                                                    unsigned long long b) {
    unsigned long long r;
    asm("mul.rn.f32x2 %0, %1, %2;" : "=l"(r) : "l"(a), "l"(b));
    return r;
}
__device__ __forceinline__ float ex2_(float x) {
    float r; asm("ex2.approx.f32 %0, %1;" : "=f"(r) : "f"(x)); return r;
}
__device__ __forceinline__ float rcp_(float x) {
    float r; asm("rcp.approx.f32 %0, %1;" : "=f"(r) : "f"(x)); return r;
}

struct Chain {
    unsigned long long plo2[8];  // packed low-nibble subset products
    float u0, u1, u2, u3;        // high-nibble variables
    float p1, p2, p3, p4;        // streaming Horner pendings (levels 1..4)
};

__device__ __forceinline__ void build_chain(const float s[8], Chain& o) {
    // mask rows are MSB-first: bit i of v  <->  s[7-i]
    float t0 = s[7], t1 = s[6], t2 = s[5], t3 = s[4];  // low nibble vars
    o.u0 = s[3]; o.u1 = s[2]; o.u2 = s[1]; o.u3 = s[0];

    float Plo[16];
    Plo[0] = 1.f;      Plo[1] = t0;           Plo[2] = t1;           Plo[3] = t1 * t0;
    Plo[4] = t2;       Plo[5] = t2 * t0;      Plo[6] = t2 * t1;      Plo[7] = t2 * Plo[3];
    Plo[8] = t3;       Plo[9] = t3 * t0;      Plo[10] = t3 * t1;     Plo[11] = t3 * Plo[3];
    Plo[12] = t3 * t2; Plo[13] = t3 * Plo[5]; Plo[14] = t3 * Plo[6]; Plo[15] = t3 * Plo[7];
#pragma unroll
    for (int j = 0; j < 8; j++) o.plo2[j] = pk2(Plo[2 * j], Plo[2 * j + 1]);
}

// Streaming Horner absorb of g[hi] (hi = 0..15 in order). Compile-time hi after
// unroll -> all branches fold. After hi==15, o.p4 holds the final y.
__device__ __forceinline__ void absorb(Chain& o, float g, int hi) {
    if ((hi & 1) == 0) { o.p1 = g; return; }
    float t1v = fmaf(o.u0, g, o.p1);                 // combine bit0 pair
    if ((hi & 2) == 0) { o.p2 = t1v; return; }
    float t2v = fmaf(o.u1, t1v, o.p2);               // combine bit1 pair
    if ((hi & 4) == 0) { o.p3 = t2v; return; }
    float t3v = fmaf(o.u2, t2v, o.p3);               // combine bit2 pair
    if (hi < 8) { o.p4 = t3v; return; }
    o.p4 = fmaf(o.u3, t3v, o.p4);                    // final: y in p4
}

__global__ __launch_bounds__(THREADS, 7)
void dendrite_kernel(const float* __restrict__ x,  const float* __restrict__ k,
                     const float* __restrict__ w,  const float* __restrict__ q,
                     const float* __restrict__ lin_w, const float* __restrict__ lin_b,
                     float* __restrict__ out)
{
    __shared__ __align__(16) float sA[256];   // -k*w*log2e, [d*8+j]
    __shared__ __align__(16) float sC[256];   //  k*q*log2e, [d*8+j]
    __shared__ __align__(16) float sLW[256];  // LWv: [0]=bias, [v]=lin_w[v-1]

    const int tid = threadIdx.x;
    const float LOG2E = 1.4426950408889634f;

    // ---- cooperative table build (128 threads cover 256 entries) ----
#pragma unroll
    for (int i = tid; i < 256; i += THREADS) {
        float kk = k[i] * LOG2E;
        sA[i] = -kk * w[i];
        sC[i] =  kk * q[i];
        sLW[i] = (i == 0) ? lin_b[0] : lin_w[i - 1];
    }
    __syncthreads();

    const int d  = tid & 31;   // lane = d
    const int bl = tid >> 5;   // warp = local b-pair index

    // per-d sigmoid coefficients (shared by both b's of this thread)
    float4 a0 = *(const float4*)(sA + d * 8);
    float4 a1 = *(const float4*)(sA + d * 8 + 4);
    float4 c0 = *(const float4*)(sC + d * 8);
    float4 c1 = *(const float4*)(sC + d * 8 + 4);
    float av[8] = {a0.x, a0.y, a0.z, a0.w, a1.x, a1.y, a1.z, a1.w};
    float cv[8] = {c0.x, c0.y, c0.z, c0.w, c1.x, c1.y, c1.z, c1.w};

    // two x rows directly from global (L2-hot broadcast; 16 consecutive floats)
    const float* xr = x + (blockIdx.x * BPB + bl * 2) * 8;
    float4 xA0 = __ldg((const float4*)(xr));
    float4 xB0 = __ldg((const float4*)(xr + 4));
    float4 xA1 = __ldg((const float4*)(xr + 8));
    float4 xB1 = __ldg((const float4*)(xr + 12));
    float xv0[8] = {xA0.x, xA0.y, xA0.z, xA0.w, xB0.x, xB0.y, xB0.z, xB0.w};
    float xv1[8] = {xA1.x, xA1.y, xA1.z, xA1.w, xB1.x, xB1.y, xB1.z, xB1.w};

    // ---- sigmoids: s = 1/(1 + 2^(A*x + C)), A=-k*w*log2e, C=k*q*log2e ----
    float s0[8], s1[8];
#pragma unroll
    for (int j = 0; j < 8; j++) {
        s0[j] = rcp_(1.0f + ex2_(fmaf(av[j], xv0[j], cv[j])));
        s1[j] = rcp_(1.0f + ex2_(fmaf(av[j], xv1[j], cv[j])));
    }

    Chain p0, p1;
    build_chain(s0, p0);
    build_chain(s1, p1);

    // ---- main: per hi, packed dot row_hi . Plo, then streaming Horner ----
    const uint32_t lwbase = (uint32_t)__cvta_generic_to_shared(sLW);
#pragma unroll
    for (int hi = 0; hi < 16; hi++) {
        unsigned long long l0, l1, l2, l3, l4, l5, l6, l7;
        uint32_t a = lwbase + hi * 64;
        asm("ld.shared.v2.u64 {%0,%1}, [%2];" : "=l"(l0), "=l"(l1) : "r"(a));
        asm("ld.shared.v2.u64 {%0,%1}, [%2];" : "=l"(l2), "=l"(l3) : "r"(a + 16));
        asm("ld.shared.v2.u64 {%0,%1}, [%2];" : "=l"(l4), "=l"(l5) : "r"(a + 32));
        asm("ld.shared.v2.u64 {%0,%1}, [%2];" : "=l"(l6), "=l"(l7) : "r"(a + 48));

        unsigned long long acc0 = mul2_(l0, p0.plo2[0]);
        unsigned long long acc1 = mul2_(l0, p1.plo2[0]);
        acc0 = fma2(l1, p0.plo2[1], acc0);  acc1 = fma2(l1, p1.plo2[1], acc1);
        acc0 = fma2(l2, p0.plo2[2], acc0);  acc1 = fma2(l2, p1.plo2[2], acc1);
        acc0 = fma2(l3, p0.plo2[3], acc0);  acc1 = fma2(l3, p1.plo2[3], acc1);
        acc0 = fma2(l4, p0.plo2[4], acc0);  acc1 = fma2(l4, p1.plo2[4], acc1);
        acc0 = fma2(l5, p0.plo2[5], acc0);  acc1 = fma2(l5, p1.plo2[5], acc1);
        acc0 = fma2(l6, p0.plo2[6], acc0);  acc1 = fma2(l6, p1.plo2[6], acc1);
        acc0 = fma2(l7, p0.plo2[7], acc0);  acc1 = fma2(l7, p1.plo2[7], acc1);

        float g0l, g0h, g1l, g1h;
        upk2(acc0, g0l, g0h);   // register-pair aliasing: no SASS cost
        upk2(acc1, g1l, g1h);
        absorb(p0, g0l + g0h, hi);
        absorb(p1, g1l + g1h, hi);
    }

    const int b0 = blockIdx.x * BPB + bl * 2;
    out[(b0 + 0) * 32 + d] = p0.p4;   // output layout [B,1,D] -> b*D + d
    out[(b0 + 1) * 32 + d] = p1.p4;
}

extern "C" void kernel_launch(void* const* d_in, const int* in_sizes, int n_in,
                              void* d_out, int out_size)
{
    const float* x     = (const float*)d_in[0];
    const float* k     = (const float*)d_in[1];
    const float* w     = (const float*)d_in[2];
    const float* q     = (const float*)d_in[3];
    // d_in[4] = mask: unused — its structure (binary expansion of 1..255,
    // MSB-first) is baked into the subset-product / Horner formulation.
    const float* lin_w = (const float*)d_in[5];
    const float* lin_b = (const float*)d_in[6];
    float* out = (float*)d_out;

    // B=8192, D=32; 8 b's per 128-thread block -> 1024 blocks, 2 (b,d)/thread.
    dendrite_kernel<<<8192 / BPB, THREADS>>>(x, k, w, q, lin_w, lin_b, out);
}

// round 15
// speedup vs baseline: 1.0030x; 1.0030x over previous
#include <cuda_runtime.h>
#include <cstdint>

// Dendrite_54417235641041 — GB300 sm_103a
// y[b,d] = sum_{v=0..255} LWv[v] * prod_{i in bits(v)} t_i,  t_i = sigmoid(k*(w*x-q))[7-i]
// LWv[0] = lin_b, LWv[v] = lin_w[v-1].
// R15: latency attack. Each 16-entry row dot (row_hi . Plo) is computed as two
// independent 4-deep packed fma2 halves + one add.f32x2 (row RAW latency
// 36 -> ~24 cyc, 4 independent chains in flight across the 2 outputs).
// launch_bounds(128,6) (~84 regs) gives ptxas room to pipeline next row's LDS.
// High nibble absorbed by a streaming 4-level Horner tree (15 scalar FMA).

#define THREADS 128
#define BPB 8   // b-values per block: 4 warps x 2 b each; lane = d

__device__ __forceinline__ unsigned long long pk2(float lo, float hi) {
    unsigned long long r;
    asm("mov.b64 %0, {%1, %2};" : "=l"(r) : "f"(lo), "f"(hi));
    return r;
}
__device__ __forceinline__ void upk2(unsigned long long v, float& lo, float& hi) {
    asm("mov.b64 {%0, %1}, %2;" : "=f"(lo), "=f"(hi) : "l"(v));
}
__device__ __forceinline__ unsigned long long fma2(unsigned long long a,
                                                   unsigned long long b,
                                                   unsigned long long c) {
    unsigned long long r;
    asm("fma.rn.f32x2 %0, %1, %2, %3;" : "=l"(r) : "l"(a), "l"(b), "l"(c));
    return r;
}
__device__ __forceinline__ unsigned long long mul2_(unsigned long long a,
                                                    unsigned long long b) {
    unsigned long long r;
    asm("mul.rn.f32x2 %0, %1, %2;" : "=l"(r) : "l"(a), "l"(b));
    return r;
}
__device__ __forceinline__ unsigned long long add2_(unsigned long long a,
                                                    unsigned long long b) {
    unsigned long long r;
    asm("add.rn.f32x2 %0, %1, %2;" : "=l"(r) : "l"(a), "l"(b));
    return r;
}
__device__ __forceinline__ float ex2_(float x) {
    float r; asm("ex2.approx.f32 %0, %1;" : "=f"(r) : "f"(x)); return r;
}
__device__ __forceinline__ float rcp_(float x) {
    float r; asm("rcp.approx.f32 %0, %1;" : "=f"(r) : "f"(x)); return r;
}

struct Chain {
    unsigned long long plo2[8];  // packed low-nibble subset products
    float u0, u1, u2, u3;        // high-nibble variables
    float p1, p2, p3, p4;        // streaming Horner pendings (levels 1..4)
};

__device__ __forceinline__ void build_chain(const float s[8], Chain& o) {
    // mask rows are MSB-first: bit i of v  <->  s[7-i]
    float t0 = s[7], t1 = s[6], t2 = s[5], t3 = s[4];  // low nibble vars
    o.u0 = s[3]; o.u1 = s[2]; o.u2 = s[1]; o.u3 = s[0];

    float Plo[16];
    Plo[0] = 1.f;      Plo[1] = t0;           Plo[2] = t1;           Plo[3] = t1 * t0;
    Plo[4] = t2;       Plo[5] = t2 * t0;      Plo[6] = t2 * t1;      Plo[7] = t2 * Plo[3];
    Plo[8] = t3;       Plo[9] = t3 * t0;      Plo[10] = t3 * t1;     Plo[11] = t3 * Plo[3];
    Plo[12] = t3 * t2; Plo[13] = t3 * Plo[5]; Plo[14] = t3 * Plo[6]; Plo[15] = t3 * Plo[7];
#pragma unroll
    for (int j = 0; j < 8; j++) o.plo2[j] = pk2(Plo[2 * j], Plo[2 * j + 1]);
}

// Streaming Horner absorb of g[hi] (hi = 0..15 in order). Compile-time hi after
// unroll -> all branches fold. After hi==15, o.p4 holds the final y.
__device__ __forceinline__ void absorb(Chain& o, float g, int hi) {
    if ((hi & 1) == 0) { o.p1 = g; return; }
    float t1v = fmaf(o.u0, g, o.p1);                 // combine bit0 pair
    if ((hi & 2) == 0) { o.p2 = t1v; return; }
    float t2v = fmaf(o.u1, t1v, o.p2);               // combine bit1 pair
    if ((hi & 4) == 0) { o.p3 = t2v; return; }
    float t3v = fmaf(o.u2, t2v, o.p3);               // combine bit2 pair
    if (hi < 8) { o.p4 = t3v; return; }
    o.p4 = fmaf(o.u3, t3v, o.p4);                    // final: y in p4
}

__global__ __launch_bounds__(THREADS, 6)
void dendrite_kernel(const float* __restrict__ x,  const float* __restrict__ k,
                     const float* __restrict__ w,  const float* __restrict__ q,
                     const float* __restrict__ lin_w, const float* __restrict__ lin_b,
                     float* __restrict__ out)
{
    __shared__ __align__(16) float sA[256];   // -k*w*log2e, [d*8+j]
    __shared__ __align__(16) float sC[256];   //  k*q*log2e, [d*8+j]
    __shared__ __align__(16) float sLW[256];  // LWv: [0]=bias, [v]=lin_w[v-1]

    const int tid = threadIdx.x;
    const float LOG2E = 1.4426950408889634f;

    // ---- cooperative table build (128 threads cover 256 entries) ----
#pragma unroll
    for (int i = tid; i < 256; i += THREADS) {
        float kk = k[i] * LOG2E;
        sA[i] = -kk * w[i];
        sC[i] =  kk * q[i];
        sLW[i] = (i == 0) ? lin_b[0] : lin_w[i - 1];
    }
    __syncthreads();

    const int d  = tid & 31;   // lane = d
    const int bl = tid >> 5;   // warp = local b-pair index

    // per-d sigmoid coefficients (shared by both b's of this thread)
    float4 a0 = *(const float4*)(sA + d * 8);
    float4 a1 = *(const float4*)(sA + d * 8 + 4);
    float4 c0 = *(const float4*)(sC + d * 8);
    float4 c1 = *(const float4*)(sC + d * 8 + 4);
    float av[8] = {a0.x, a0.y, a0.z, a0.w, a1.x, a1.y, a1.z, a1.w};
    float cv[8] = {c0.x, c0.y, c0.z, c0.w, c1.x, c1.y, c1.z, c1.w};

    // two x rows directly from global (L2-hot broadcast; 16 consecutive floats)
    const float* xr = x + (blockIdx.x * BPB + bl * 2) * 8;
    float4 xA0 = __ldg((const float4*)(xr));
    float4 xB0 = __ldg((const float4*)(xr + 4));
    float4 xA1 = __ldg((const float4*)(xr + 8));
    float4 xB1 = __ldg((const float4*)(xr + 12));
    float xv0[8] = {xA0.x, xA0.y, xA0.z, xA0.w, xB0.x, xB0.y, xB0.z, xB0.w};
    float xv1[8] = {xA1.x, xA1.y, xA1.z, xA1.w, xB1.x, xB1.y, xB1.z, xB1.w};

    // ---- sigmoids: s = 1/(1 + 2^(A*x + C)), A=-k*w*log2e, C=k*q*log2e ----
    float s0[8], s1[8];
#pragma unroll
    for (int j = 0; j < 8; j++) {
        s0[j] = rcp_(1.0f + ex2_(fmaf(av[j], xv0[j], cv[j])));
        s1[j] = rcp_(1.0f + ex2_(fmaf(av[j], xv1[j], cv[j])));
    }

    Chain p0, p1;
    build_chain(s0, p0);
    build_chain(s1, p1);

    // ---- main: per hi, split-dot row_hi . Plo (two 4-deep halves + add2),
    //      then streaming Horner absorb ----
    const uint32_t lwbase = (uint32_t)__cvta_generic_to_shared(sLW);
#pragma unroll
    for (int hi = 0; hi < 16; hi++) {
        unsigned long long l0, l1, l2, l3, l4, l5, l6, l7;
        uint32_t a = lwbase + hi * 64;
        asm("ld.shared.v2.u64 {%0,%1}, [%2];" : "=l"(l0), "=l"(l1) : "r"(a));
        asm("ld.shared.v2.u64 {%0,%1}, [%2];" : "=l"(l2), "=l"(l3) : "r"(a + 16));
        asm("ld.shared.v2.u64 {%0,%1}, [%2];" : "=l"(l4), "=l"(l5) : "r"(a + 32));
        asm("ld.shared.v2.u64 {%0,%1}, [%2];" : "=l"(l6), "=l"(l7) : "r"(a + 48));

        // chain 0: two independent 4-deep halves
        unsigned long long a0A = mul2_(l0, p0.plo2[0]);
        unsigned long long a0B = mul2_(l4, p0.plo2[4]);
        // chain 1: two independent 4-deep halves
        unsigned long long a1A = mul2_(l0, p1.plo2[0]);
        unsigned long long a1B = mul2_(l4, p1.plo2[4]);

        a0A = fma2(l1, p0.plo2[1], a0A);  a0B = fma2(l5, p0.plo2[5], a0B);
        a1A = fma2(l1, p1.plo2[1], a1A);  a1B = fma2(l5, p1.plo2[5], a1B);
        a0A = fma2(l2, p0.plo2[2], a0A);  a0B = fma2(l6, p0.plo2[6], a0B);
        a1A = fma2(l2, p1.plo2[2], a1A);  a1B = fma2(l6, p1.plo2[6], a1B);
        a0A = fma2(l3, p0.plo2[3], a0A);  a0B = fma2(l7, p0.plo2[7], a0B);
        a1A = fma2(l3, p1.plo2[3], a1A);  a1B = fma2(l7, p1.plo2[7], a1B);

        unsigned long long acc0 = add2_(a0A, a0B);
        unsigned long long acc1 = add2_(a1A, a1B);

        float g0l, g0h, g1l, g1h;
        upk2(acc0, g0l, g0h);   // register-pair aliasing: no SASS cost
        upk2(acc1, g1l, g1h);
        absorb(p0, g0l + g0h, hi);
        absorb(p1, g1l + g1h, hi);
    }

    const int b0 = blockIdx.x * BPB + bl * 2;
    out[(b0 + 0) * 32 + d] = p0.p4;   // output layout [B,1,D] -> b*D + d
    out[(b0 + 1) * 32 + d] = p1.p4;
}

extern "C" void kernel_launch(void* const* d_in, const int* in_sizes, int n_in,
                              void* d_out, int out_size)
{
    const float* x     = (const float*)d_in[0];
    const float* k     = (const float*)d_in[1];
    const float* w     = (const float*)d_in[2];
    const float* q     = (const float*)d_in[3];
    // d_in[4] = mask: unused — its structure (binary expansion of 1..255,
    // MSB-first) is baked into the subset-product / Horner formulation.
    const float* lin_w = (const float*)d_in[5];
    const float* lin_b = (const float*)d_in[6];
    float* out = (float*)d_out;

    // B=8192, D=32; 8 b's per 128-thread block -> 1024 blocks, 2 (b,d)/thread.
    dendrite_kernel<<<8192 / BPB, THREADS>>>(x, k, w, q, lin_w, lin_b, out);
}